// round 11
// baseline (speedup 1.0000x reference)
#include <cuda_runtime.h>
#include <cuda_bf16.h>

#define BATCH 32
#define NAG   6
#define KS    256
#define QS    256
#define CHW   (512*32*32)       /* 524288 floats per (b,n) slab */
#define V4PB  (CHW/4)           /* 131072 float4 per (b,n) slab */
#define CHUNKS 8                /* attn kk-chunks per batch (32 rows each) */
#define WSB   128               /* wsum blocks per batch (grid 4096 / 32) */

typedef unsigned long long u64;

// Scratch (allocation-free rule: __device__ globals). Zero-initialized at
// module load; all state is reset in-kernel so graph replays are identical.
__device__ float                 g_attn[BATCH * NAG];
__device__ float                 g_score[BATCH * NAG];
__device__ unsigned int          g_cnt[BATCH];
__device__ unsigned int          g_done[BATCH];
__device__ volatile u64          g_pack[BATCH];   // 0 = not ready;
                                                  // hi32: 1..6 = n0+1, 7 = multi
                                                  // lo32: float bits of w[n0]

// ---------------------------------------------------------------------------
// Fused kernel, grid = 4096 x 256 (non-persistent wsum mapping, R4-exact).
//  * blocks 0..255: attn chunk -> partial scores -> ticketed sparsemax ->
//      publish g_attn + one packed u64 per batch (single-word handoff).
//  * all blocks: per-thread poll of the packed word (no smem, no barriers),
//      then 4x float4 weighted sum. k==1 (dominant): scale-copy using the
//      packed weight. k>=2 (rare): full 6-agent accumulate via __ldcg.
//  * per-batch done counters reset the pack for the next graph replay.
// ---------------------------------------------------------------------------
__global__ void __launch_bounds__(256)
fused_kernel(const float* __restrict__ q,
             const float* __restrict__ k,
             const float* __restrict__ v,
             const float* __restrict__ W,
             const float* __restrict__ bias,
             float* __restrict__ out,
             float* __restrict__ out_attn,
             int write_attn) {
    const int bid  = blockIdx.x;
    const int t    = threadIdx.x;
    const int wid  = t >> 5, lane = t & 31;

    // ================= attn phase (blocks 0..255 only) ====================
    if (bid < BATCH * CHUNKS) {
        __shared__ float4 sq4[QS / 4];
        __shared__ float  squery[32];

        const int ab     = bid >> 3;
        const int kkbase = (bid & 7) << 5;

        if (t < QS / 4) sq4[t] = ((const float4*)(q + ab * QS))[t];
        __syncthreads();

        // warp `wid` computes 4 query rows, 2 at a time
        {
            const int r0 = kkbase + (wid << 2);
            const float4 q0 = sq4[lane], q1 = sq4[lane + 32];
            #pragma unroll
            for (int h = 0; h < 2; h++) {
                const int ra = r0 + 2 * h;
                const float4* wa = (const float4*)(W + ra * QS);
                const float4* wb = (const float4*)(W + (ra + 1) * QS);
                float4 a0 = wa[lane], a1 = wa[lane + 32];
                float4 b0 = wb[lane], b1 = wb[lane + 32];
                float sa = a0.x * q0.x + a0.y * q0.y + a0.z * q0.z + a0.w * q0.w
                         + a1.x * q1.x + a1.y * q1.y + a1.z * q1.z + a1.w * q1.w;
                float sb = b0.x * q0.x + b0.y * q0.y + b0.z * q0.z + b0.w * q0.w
                         + b1.x * q1.x + b1.y * q1.y + b1.z * q1.z + b1.w * q1.w;
                #pragma unroll
                for (int o = 16; o; o >>= 1) {
                    sa += __shfl_xor_sync(0xffffffffu, sa, o);
                    sb += __shfl_xor_sync(0xffffffffu, sb, o);
                }
                if (lane == 0) {
                    squery[(wid << 2) + 2 * h]     = sa + bias[ra];
                    squery[(wid << 2) + 2 * h + 1] = sb + bias[ra + 1];
                }
            }
        }
        __syncthreads();

        // 6 warps -> partial agent scores
        if (wid < NAG) {
            float p = k[(ab * NAG + wid) * KS + kkbase + lane] * squery[lane];
            #pragma unroll
            for (int o = 16; o; o >>= 1) p += __shfl_xor_sync(0xffffffffu, p, o);
            if (lane == 0) atomicAdd(&g_score[ab * NAG + wid], p);
        }

        __threadfence();
        if (t == 0 && atomicAdd(&g_cnt[ab], 1u) == CHUNKS - 1) {
            __threadfence();                      // acquire all partials
            float z[NAG], zs[NAG];
            #pragma unroll
            for (int n = 0; n < NAG; n++) {
                z[n] = g_score[ab * NAG + n];
                zs[n] = z[n];
                g_score[ab * NAG + n] = 0.0f;     // reset for next replay
            }
            g_cnt[ab] = 0u;
            #pragma unroll
            for (int i = 1; i < NAG; i++) {       // insertion sort, descending
                float key = zs[i]; int j = i - 1;
                while (j >= 0 && zs[j] < key) { zs[j + 1] = zs[j]; j--; }
                zs[j + 1] = key;
            }
            float cs[NAG], run = 0.f;
            #pragma unroll
            for (int r = 0; r < NAG; r++) { run += zs[r]; cs[r] = run; }
            int kk = 0;
            #pragma unroll
            for (int r = 1; r <= NAG; r++)
                if (1.0f + (float)r * zs[r - 1] > cs[r - 1]) kk++;
            const float tau = (cs[kk - 1] - 1.0f) / (float)kk;

            int   nz = 0, n0 = 0;
            float w0 = 0.0f;
            #pragma unroll
            for (int n = 0; n < NAG; n++) {
                float p = fmaxf(z[n] - tau, 0.0f);
                g_attn[ab * NAG + n] = p;
                if (write_attn) out_attn[ab * NAG + n] = p;
                if (p != 0.0f) { if (nz == 0) { n0 = n; w0 = p; } nz++; }
            }
            const unsigned code = (nz == 1) ? (unsigned)(n0 + 1) : 7u;
            __threadfence();                      // publish weights first
            g_pack[ab] = ((u64)code << 32) | (u64)__float_as_uint(w0);
        }
        __syncthreads();
    }

    // ================= wsum phase (all 4096 blocks) ========================
    const int b    = bid >> 7;                          // 128 blocks/batch
    const int base = ((bid & 127) << 10) + t;           // float4 idx in slab

    // single-word handoff: per-thread poll, warp-coalesced, no barriers
    u64 pk;
    while ((pk = g_pack[b]) == 0ull) __nanosleep(32);
    const int code = (int)(pk >> 32);

    const float4* vbase = (const float4*)v + (b * (NAG * V4PB) + base);
    float4*       ob    = (float4*)out    + (b * V4PB + base);

    if (code <= NAG) {
        // ---- dominant path: single nonzero agent -> scale-copy -----------
        const float w = __uint_as_float((unsigned)pk);
        const float4* p = vbase + (code - 1) * V4PB;
        float4 x0 = p[0];
        float4 x1 = p[256];
        float4 x2 = p[512];
        float4 x3 = p[768];
        float4 r0, r1, r2, r3;
        r0.x = w * x0.x; r0.y = w * x0.y; r0.z = w * x0.z; r0.w = w * x0.w;
        r1.x = w * x1.x; r1.y = w * x1.y; r1.z = w * x1.z; r1.w = w * x1.w;
        r2.x = w * x2.x; r2.y = w * x2.y; r2.z = w * x2.z; r2.w = w * x2.w;
        r3.x = w * x3.x; r3.y = w * x3.y; r3.z = w * x3.z; r3.w = w * x3.w;
        ob[0]   = r0;
        ob[256] = r1;
        ob[512] = r2;
        ob[768] = r3;
    } else {
        // ---- rare path: multi-agent accumulate (R4-style) -----------------
        float4 acc0 = make_float4(0.f, 0.f, 0.f, 0.f);
        float4 acc1 = acc0, acc2 = acc0, acc3 = acc0;
        #pragma unroll
        for (int n = 0; n < NAG; n++) {
            const float w = __ldcg(&g_attn[b * NAG + n]);
            if (w != 0.0f) {                      // block-uniform branch
                const float4* p = vbase + n * V4PB;
                float4 x0 = p[0];
                float4 x1 = p[256];
                float4 x2 = p[512];
                float4 x3 = p[768];
                acc0.x = fmaf(w, x0.x, acc0.x); acc0.y = fmaf(w, x0.y, acc0.y);
                acc0.z = fmaf(w, x0.z, acc0.z); acc0.w = fmaf(w, x0.w, acc0.w);
                acc1.x = fmaf(w, x1.x, acc1.x); acc1.y = fmaf(w, x1.y, acc1.y);
                acc1.z = fmaf(w, x1.z, acc1.z); acc1.w = fmaf(w, x1.w, acc1.w);
                acc2.x = fmaf(w, x2.x, acc2.x); acc2.y = fmaf(w, x2.y, acc2.y);
                acc2.z = fmaf(w, x2.z, acc2.z); acc2.w = fmaf(w, x2.w, acc2.w);
                acc3.x = fmaf(w, x3.x, acc3.x); acc3.y = fmaf(w, x3.y, acc3.y);
                acc3.z = fmaf(w, x3.z, acc3.z); acc3.w = fmaf(w, x3.w, acc3.w);
            }
        }
        ob[0]   = acc0;
        ob[256] = acc1;
        ob[512] = acc2;
        ob[768] = acc3;
    }

    // -------- per-batch cleanup so the next graph replay starts clean ------
    __syncthreads();       // all threads have consumed g_pack[b]
    if (t == 0 && atomicAdd(&g_done[b], 1u) == WSB - 1) {
        g_done[b] = 0u;
        g_pack[b] = 0ull;
    }
}

// ---------------------------------------------------------------------------
extern "C" void kernel_launch(void* const* d_in, const int* in_sizes, int n_in,
                              void* d_out, int out_size) {
    const float* q    = (const float*)d_in[0];
    const float* k    = (const float*)d_in[1];
    const float* v    = (const float*)d_in[2];
    const float* W    = (const float*)d_in[3];
    const float* bias = (const float*)d_in[4];

    float* out = (float*)d_out;
    const long long out_main = (long long)BATCH * CHW;        // 16777216
    const int write_attn = (out_size >= out_main + BATCH * NAG) ? 1 : 0;
    float* out_attn = out + out_main;

    const int blocks = (BATCH * V4PB) / (256 * 4);            // 4096
    fused_kernel<<<blocks, 256>>>(q, k, v, W, bias, out, out_attn, write_attn);
}